// round 7
// baseline (speedup 1.0000x reference)
#include <cuda_runtime.h>
#include <cstdint>

// Gated delta-rule recurrent attention, single step. B=128, H=16, Dk=Dv=128.
//
// Round-6: finer phase granularity. Round-5 confirmed DRAM% scales with
// CTA-level phase interleaving (63% -> 71% going 2 fat CTAs/SM -> 8 small).
// This round: same 32-col slices (one 128B line per row -> perfect
// coalescing), but 256 threads/CTA with 4-row patches and 5 CTAs/SM
// (40 warps). Shorter per-CTA load/store bursts, more concurrent CTAs
// weaving the DRAM request stream.
//
// Thread (rg, c4): rg = tid>>3 (32 row groups of 4 rows), c4 = tid&7
// (float4 column in the 32-col slice). State patch: 4x float4 registers,
// read once (__ldcs evict-first), written once (__stcs evict-first).

#define BH   2048
#define DK   128
#define DV   128

__global__ __launch_bounds__(256, 5)
void delta_cell_kernel(const float* __restrict__ q,
                       const float* __restrict__ k,
                       const float* __restrict__ v,
                       const float* __restrict__ g,
                       const float* __restrict__ beta,
                       const float* __restrict__ state_in,
                       float* __restrict__ out,
                       float* __restrict__ state_out)
{
    const int bid = blockIdx.x;          // 0..8191
    const int bh  = bid >> 2;            // (b*H + h)
    const int cb  = bid & 3;             // column block: cols [cb*32, cb*32+32)
    const int tid = threadIdx.x;
    const int c4  = tid & 7;             // float4 col within slice (0..7)
    const int rg  = tid >> 3;            // row group (0..31), rows 4rg..4rg+3

    __shared__ float  ks[DK];
    __shared__ float  qs[DK];
    __shared__ float4 red_kv [32][8];
    __shared__ float4 red_out[32][8];

    if (tid < DK) {
        ks[tid] = k[bh * DK + tid];
        qs[tid] = q[bh * DK + tid];
    }
    __syncthreads();

    const float decay = expf(g[bh]);
    const float bet   = beta[bh];
    const float4 vt   = ((const float4*)(v + (size_t)bh * DV))[cb * 8 + c4];

    const float4* __restrict__ st4 =
        (const float4*)(state_in  + (size_t)bh * DK * DV);
    float4* __restrict__ sto4 =
        (float4*)(state_out + (size_t)bh * DK * DV);
    const int colbase = cb * 8 + c4;     // float4 column in the 32-wide row

    // ---- Pass 1: load the thread's 4x4 patch (raw), partial k-dot ----
    float4 s[4];
    float4 kv = make_float4(0.f, 0.f, 0.f, 0.f);
#pragma unroll
    for (int j = 0; j < 4; ++j) {
        const int row = rg * 4 + j;
        const float4 x = __ldcs(&st4[row * 32 + colbase]);
        s[j] = x;
        const float kk = ks[row];
        kv.x = fmaf(x.x, kk, kv.x);
        kv.y = fmaf(x.y, kk, kv.y);
        kv.z = fmaf(x.z, kk, kv.z);
        kv.w = fmaf(x.w, kk, kv.w);
    }
    red_kv[rg][c4] = kv;
    __syncthreads();

    // Reduce the 32 row-group partials (redundantly in every thread)
    float4 kvt = make_float4(0.f, 0.f, 0.f, 0.f);
#pragma unroll
    for (int gg = 0; gg < 32; ++gg) {
        const float4 p = red_kv[gg][c4];
        kvt.x += p.x; kvt.y += p.y; kvt.z += p.z; kvt.w += p.w;
    }
    // kv_mem = decay * (state . k); delta = (v - kv_mem) * beta
    float4 delta;
    delta.x = (vt.x - decay * kvt.x) * bet;
    delta.y = (vt.y - decay * kvt.y) * bet;
    delta.z = (vt.z - decay * kvt.z) * bet;
    delta.w = (vt.w - decay * kvt.w) * bet;

    // ---- Pass 2: sn = decay*state + k*delta, store, partial q-dot ----
    float4 acc = make_float4(0.f, 0.f, 0.f, 0.f);
#pragma unroll
    for (int j = 0; j < 4; ++j) {
        const int row = rg * 4 + j;
        const float kk = ks[row];
        float4 sn;
        sn.x = fmaf(decay, s[j].x, kk * delta.x);
        sn.y = fmaf(decay, s[j].y, kk * delta.y);
        sn.z = fmaf(decay, s[j].z, kk * delta.z);
        sn.w = fmaf(decay, s[j].w, kk * delta.w);
        __stcs(&sto4[row * 32 + colbase], sn);
        const float qq = qs[row];
        acc.x = fmaf(sn.x, qq, acc.x);
        acc.y = fmaf(sn.y, qq, acc.y);
        acc.z = fmaf(sn.z, qq, acc.z);
        acc.w = fmaf(sn.w, qq, acc.w);
    }
    red_out[rg][c4] = acc;
    __syncthreads();

    // Row-group 0 (tids 0..7) finishes the q-dot and writes the output cols
    if (rg == 0) {
        float4 o = make_float4(0.f, 0.f, 0.f, 0.f);
#pragma unroll
        for (int gg = 0; gg < 32; ++gg) {
            const float4 p = red_out[gg][c4];
            o.x += p.x; o.y += p.y; o.z += p.z; o.w += p.w;
        }
        ((float4*)(out + (size_t)bh * DV))[cb * 8 + c4] = o;
    }
}

extern "C" void kernel_launch(void* const* d_in, const int* in_sizes, int n_in,
                              void* d_out, int out_size)
{
    const float* q     = (const float*)d_in[0];  // (B,H,1,Dk)
    const float* k     = (const float*)d_in[1];  // (B,H,1,Dk)
    const float* v     = (const float*)d_in[2];  // (B,H,1,Dv)
    const float* g     = (const float*)d_in[3];  // (B,H,1)
    const float* beta  = (const float*)d_in[4];  // (B,H,1)
    const float* state = (const float*)d_in[5];  // (B,H,Dk,Dv)

    float* out       = (float*)d_out;            // first B*H*Dv floats
    float* state_out = out + (size_t)BH * DV;    // then B*H*Dk*Dv floats

    delta_cell_kernel<<<BH * 4, 256>>>(q, k, v, g, beta, state,
                                       out, state_out);
}

// round 9
// speedup vs baseline: 1.3816x; 1.3816x over previous
#include <cuda_runtime.h>
#include <cstdint>

// Gated delta-rule recurrent attention, single step. B=128, H=16, Dk=Dv=128.
//
// Round-7 = round-5 (best: 45.6us, DRAM 71%) + shorter reduction epochs.
// Round-6 taught: DRAM% tracks per-thread front-batched load depth (MLP-8
// beats MLP-4 even at higher occupancy) and LDS reduction traffic throttles
// the load loop. So: keep 8192 CTAs x 128 threads / 32-col slices / MLP-8,
// but collapse the 4 row-groups inside each warp with shfl_xor before smem
// (16 -> 4 partials), and use evict-first stores.

#define BH   2048
#define DK   128
#define DV   128

__global__ __launch_bounds__(128, 8)
void delta_cell_kernel(const float* __restrict__ q,
                       const float* __restrict__ k,
                       const float* __restrict__ v,
                       const float* __restrict__ g,
                       const float* __restrict__ beta,
                       const float* __restrict__ state_in,
                       float* __restrict__ out,
                       float* __restrict__ state_out)
{
    const int bid  = blockIdx.x;         // 0..8191
    const int bh   = bid >> 2;           // (b*H + h)
    const int cb   = bid & 3;            // column block: cols [cb*32, cb*32+32)
    const int tid  = threadIdx.x;
    const int c4   = tid & 7;            // float4 col within slice (0..7)
    const int rg   = tid >> 3;           // row group (0..15), rows 8rg..8rg+7
    const int warp = tid >> 5;           // 0..3 (each warp = 4 row groups)

    __shared__ float  ks[DK];
    __shared__ float  qs[DK];
    __shared__ float4 red_kv [4][8];     // one partial per warp per c4
    __shared__ float4 red_out[4][8];

    ks[tid] = k[bh * DK + tid];
    qs[tid] = q[bh * DK + tid];
    __syncthreads();

    const float decay = expf(g[bh]);
    const float bet   = beta[bh];
    const float4 vt   = ((const float4*)(v + (size_t)bh * DV))[cb * 8 + c4];

    const float4* __restrict__ st4 =
        (const float4*)(state_in  + (size_t)bh * DK * DV);
    float4* __restrict__ sto4 =
        (float4*)(state_out + (size_t)bh * DK * DV);
    const int colbase = cb * 8 + c4;     // float4 column in the 32-wide row

    // ---- Pass 1: load the thread's 8x4 patch (raw), partial k-dot ----
    float4 s[8];
    float4 kv = make_float4(0.f, 0.f, 0.f, 0.f);
#pragma unroll
    for (int j = 0; j < 8; ++j) {
        const int row = rg * 8 + j;
        const float4 x = __ldcs(&st4[row * 32 + colbase]);
        s[j] = x;
        const float kk = ks[row];
        kv.x = fmaf(x.x, kk, kv.x);
        kv.y = fmaf(x.y, kk, kv.y);
        kv.z = fmaf(x.z, kk, kv.z);
        kv.w = fmaf(x.w, kk, kv.w);
    }
    // Warp-level: combine the 4 row-groups in this warp (lanes differ in
    // bits 3,4 of lane id = rg low bits; same c4 across xor 8/16).
#pragma unroll
    for (int m = 8; m <= 16; m <<= 1) {
        kv.x += __shfl_xor_sync(0xffffffffu, kv.x, m);
        kv.y += __shfl_xor_sync(0xffffffffu, kv.y, m);
        kv.z += __shfl_xor_sync(0xffffffffu, kv.z, m);
        kv.w += __shfl_xor_sync(0xffffffffu, kv.w, m);
    }
    if ((tid & 31) < 8)                  // one lane per c4 per warp
        red_kv[warp][c4] = kv;
    __syncthreads();

    // Reduce the 4 warp partials (redundantly in every thread)
    float4 kvt = make_float4(0.f, 0.f, 0.f, 0.f);
#pragma unroll
    for (int w = 0; w < 4; ++w) {
        const float4 p = red_kv[w][c4];
        kvt.x += p.x; kvt.y += p.y; kvt.z += p.z; kvt.w += p.w;
    }
    // kv_mem = decay * (state . k); delta = (v - kv_mem) * beta
    float4 delta;
    delta.x = (vt.x - decay * kvt.x) * bet;
    delta.y = (vt.y - decay * kvt.y) * bet;
    delta.z = (vt.z - decay * kvt.z) * bet;
    delta.w = (vt.w - decay * kvt.w) * bet;

    // ---- Pass 2: sn = decay*state + k*delta, store, partial q-dot ----
    float4 acc = make_float4(0.f, 0.f, 0.f, 0.f);
#pragma unroll
    for (int j = 0; j < 8; ++j) {
        const int row = rg * 8 + j;
        const float kk = ks[row];
        float4 sn;
        sn.x = fmaf(decay, s[j].x, kk * delta.x);
        sn.y = fmaf(decay, s[j].y, kk * delta.y);
        sn.z = fmaf(decay, s[j].z, kk * delta.z);
        sn.w = fmaf(decay, s[j].w, kk * delta.w);
        __stcs(&sto4[row * 32 + colbase], sn);
        const float qq = qs[row];
        acc.x = fmaf(sn.x, qq, acc.x);
        acc.y = fmaf(sn.y, qq, acc.y);
        acc.z = fmaf(sn.z, qq, acc.z);
        acc.w = fmaf(sn.w, qq, acc.w);
    }
#pragma unroll
    for (int m = 8; m <= 16; m <<= 1) {
        acc.x += __shfl_xor_sync(0xffffffffu, acc.x, m);
        acc.y += __shfl_xor_sync(0xffffffffu, acc.y, m);
        acc.z += __shfl_xor_sync(0xffffffffu, acc.z, m);
        acc.w += __shfl_xor_sync(0xffffffffu, acc.w, m);
    }
    if ((tid & 31) < 8)
        red_out[warp][c4] = acc;
    __syncthreads();

    // tids 0..7 finish the q-dot and write this slice's output columns
    if (tid < 8) {
        float4 o = make_float4(0.f, 0.f, 0.f, 0.f);
#pragma unroll
        for (int w = 0; w < 4; ++w) {
            const float4 p = red_out[w][c4];
            o.x += p.x; o.y += p.y; o.z += p.z; o.w += p.w;
        }
        ((float4*)(out + (size_t)bh * DV))[cb * 8 + c4] = o;
    }
}

extern "C" void kernel_launch(void* const* d_in, const int* in_sizes, int n_in,
                              void* d_out, int out_size)
{
    const float* q     = (const float*)d_in[0];  // (B,H,1,Dk)
    const float* k     = (const float*)d_in[1];  // (B,H,1,Dk)
    const float* v     = (const float*)d_in[2];  // (B,H,1,Dv)
    const float* g     = (const float*)d_in[3];  // (B,H,1)
    const float* beta  = (const float*)d_in[4];  // (B,H,1)
    const float* state = (const float*)d_in[5];  // (B,H,Dk,Dv)

    float* out       = (float*)d_out;            // first B*H*Dv floats
    float* state_out = out + (size_t)BH * DV;    // then B*H*Dk*Dv floats

    delta_cell_kernel<<<BH * 4, 128>>>(q, k, v, g, beta, state,
                                       out, state_out);
}